// round 3
// baseline (speedup 1.0000x reference)
#include <cuda_runtime.h>
#include <math.h>

#define B 64
#define T 512
#define E 256
#define U 256
#define Z 1024      /* 4*U */
#define CHUNK 256
#define NCHUNK (T / CHUNK)   /* 2 */

__device__ __forceinline__ float sigm(float v) { return 1.0f / (1.0f + expf(-v)); }

// One CTA per (batch, 256-timestep chunk), 128 CTAs total (one wave, 1 CTA/SM).
// Keras masked-LSTM semantics: state updates ONLY where token == 0 (mask True);
// elsewhere h/c carry through and out[b,t] is the carried h1. Hence:
//   - if no zero token exists in [0, t_end), this chunk's output block is exactly
//     zero -> single int4 prefix-load + __syncthreads_or + pure streaming stores.
//   - otherwise (rare, general-correctness path) the CTA replays the sequential
//     masked LSTM itself up to t_end; the <=2 sibling CTAs of a batch duplicate
//     identical fp work in parallel, so no inter-CTA dependency exists.
__global__ __launch_bounds__(256)
void lstm_fused_kernel(const int*   __restrict__ x,
                       const float* __restrict__ emb,
                       const float* __restrict__ k0,
                       const float* __restrict__ r0,
                       const float* __restrict__ b0,
                       const float* __restrict__ k1,
                       const float* __restrict__ r1,
                       const float* __restrict__ b1,
                       float*       __restrict__ out)
{
    const int b     = blockIdx.x >> 1;
    const int chunk = blockIdx.x & (NCHUNK - 1);
    const int t0    = chunk * CHUNK;
    const int t_end = t0 + CHUNK;
    const int j     = threadIdx.x;           // 0..255

    // ---- any zero token in [0, t_end)?  one int4 load + one barrier-or ----
    const int n4 = t_end >> 2;                // 64 or 128 int4 words
    int pred = 0;
    if (j < n4) {
        const int4 v = reinterpret_cast<const int4*>(x + (size_t)b * T)[j];
        pred = (v.x == 0) | (v.y == 0) | (v.z == 0) | (v.w == 0);
    }
    const int any = __syncthreads_or(pred);

    if (!any) {
        // ---------- common fast path: chunk output is exactly zero ----------
        const float4 zv = make_float4(0.f, 0.f, 0.f, 0.f);
        float4* dst = reinterpret_cast<float4*>(out + (size_t)b * T * U + (size_t)t0 * U);
        #pragma unroll
        for (int i = 0; i < 64; i++)          // 256*256 floats = 16384 f4 / 256 thr
            dst[i * 256 + j] = zv;
        if (chunk == NCHUNK - 1) {            // whole row inactive -> final h == 0
            float4* hdst = reinterpret_cast<float4*>(out + (size_t)B * T * U + (size_t)b * U);
            if (j < U / 4) hdst[j] = zv;
        }
        return;
    }

    // ---------- rare general path: replay the masked LSTM up to t_end ----------
    __shared__ int   acts[T];
    __shared__ float h0s[U];
    __shared__ float h1s[U];
    __shared__ float zbuf[Z];
    __shared__ float embs[E];

    for (int t = j; t < t_end; t += 256)
        acts[t] = (x[(size_t)b * T + t] == 0);

    embs[j] = emb[j];        // embedding row of token 0
    h0s[j]  = 0.0f;
    h1s[j]  = 0.0f;
    __syncthreads();

    // Constant layer-0 x-contribution: xz = emb[0,:] @ k0 + b0.
    // Thread j owns gate columns 4j..4j+3 (float4 across Z).
    float4 xz = reinterpret_cast<const float4*>(b0)[j];
    for (int e = 0; e < E; e++) {
        const float  ev = embs[e];
        const float4 kv = reinterpret_cast<const float4*>(k0 + (size_t)e * Z)[j];
        xz.x += ev * kv.x; xz.y += ev * kv.y; xz.z += ev * kv.z; xz.w += ev * kv.w;
    }
    const float4 b1v = reinterpret_cast<const float4*>(b1)[j];

    float c0 = 0.0f, c1 = 0.0f;

    for (int t = 0; t < t_end; t++) {
        if (acts[t]) {
            // ---- layer 0: z = xz + h0 @ r0 ----
            float4 z = xz;
            #pragma unroll 4
            for (int k = 0; k < U; k++) {
                const float  hv = h0s[k];
                const float4 rv = reinterpret_cast<const float4*>(r0 + (size_t)k * Z)[j];
                z.x += hv * rv.x; z.y += hv * rv.y; z.z += hv * rv.z; z.w += hv * rv.w;
            }
            reinterpret_cast<float4*>(zbuf)[j] = z;
            __syncthreads();
            {
                const float ig = sigm (zbuf[0 * U + j]);
                const float fg = sigm (zbuf[1 * U + j]);
                const float gg = tanhf(zbuf[2 * U + j]);
                const float og = sigm (zbuf[3 * U + j]);
                c0 = fg * c0 + ig * gg;
                __syncthreads();                 // matvec reads of h0s fully done
                h0s[j] = og * tanhf(c0);
            }
            __syncthreads();

            // ---- layer 1: w = b1 + h0 @ k1 + h1 @ r1 ----
            float4 w = b1v;
            #pragma unroll 2
            for (int k = 0; k < U; k++) {
                const float  h0v = h0s[k];
                const float  h1v = h1s[k];
                const float4 kv = reinterpret_cast<const float4*>(k1 + (size_t)k * Z)[j];
                const float4 rv = reinterpret_cast<const float4*>(r1 + (size_t)k * Z)[j];
                w.x += h0v * kv.x + h1v * rv.x;
                w.y += h0v * kv.y + h1v * rv.y;
                w.z += h0v * kv.z + h1v * rv.z;
                w.w += h0v * kv.w + h1v * rv.w;
            }
            __syncthreads();                     // prior zbuf reads done
            reinterpret_cast<float4*>(zbuf)[j] = w;
            __syncthreads();
            {
                const float ig = sigm (zbuf[0 * U + j]);
                const float fg = sigm (zbuf[1 * U + j]);
                const float gg = tanhf(zbuf[2 * U + j]);
                const float og = sigm (zbuf[3 * U + j]);
                c1 = fg * c1 + ig * gg;
                __syncthreads();                 // matvec reads of h1s fully done
                h1s[j] = og * tanhf(c1);
            }
            __syncthreads();
        }
        if (t >= t0)
            out[(size_t)b * T * U + (size_t)t * U + j] = h1s[j];
    }

    if (chunk == NCHUNK - 1)                     // ran the full sequence
        out[(size_t)B * T * U + (size_t)b * U + j] = h1s[j];
}

extern "C" void kernel_launch(void* const* d_in, const int* in_sizes, int n_in,
                              void* d_out, int out_size)
{
    const int*   x   = (const int*)  d_in[0];
    const float* emb = (const float*)d_in[1];
    const float* k0  = (const float*)d_in[2];
    const float* r0  = (const float*)d_in[3];
    const float* b0  = (const float*)d_in[4];
    const float* k1  = (const float*)d_in[5];
    const float* r1  = (const float*)d_in[6];
    const float* b1  = (const float*)d_in[7];
    float* out = (float*)d_out;

    lstm_fused_kernel<<<B * NCHUNK, 256>>>(x, emb, k0, r0, b0, k1, r1, b1, out);
}

// round 4
// speedup vs baseline: 1.0208x; 1.0208x over previous
#include <cuda_runtime.h>
#include <math.h>

#define B 64
#define T 512
#define E 256
#define U 256
#define Z 1024      /* 4*U */
#define CHUNK 256
#define NCHUNK (T / CHUNK)   /* 2 */

#define ZBYTES 32768         /* 32KB shared zero buffer */
#define BULKS_PER_CTA ((CHUNK * U * 4) / ZBYTES)  /* 256KB / 32KB = 8 */

__device__ __forceinline__ float sigm(float v) { return 1.0f / (1.0f + expf(-v)); }

__device__ __forceinline__ unsigned smem_u32(const void* p) {
    return (unsigned)__cvta_generic_to_shared(p);
}

// One CTA per (batch, 256-timestep chunk), 128 CTAs. Keras masked-LSTM:
// state updates ONLY where token == 0 (mask True); otherwise h/c carry through
// and out[b,t] is the carried h1.
//   - No zero token in [0, t_end)  ->  chunk output is exactly the zero vector.
//     Fast path: fill a 32KB SMEM zero buffer, then 8x cp.async.bulk
//     (shared->global) to blast the 256KB region down the TMA/LTS path,
//     bypassing the per-thread STG store-queue bottleneck seen in R1-R3.
//   - Otherwise (rare): replay the sequential masked LSTM up to t_end.
__global__ __launch_bounds__(256)
void lstm_fused_kernel(const int*   __restrict__ x,
                       const float* __restrict__ emb,
                       const float* __restrict__ k0,
                       const float* __restrict__ r0,
                       const float* __restrict__ b0,
                       const float* __restrict__ k1,
                       const float* __restrict__ r1,
                       const float* __restrict__ b1,
                       float*       __restrict__ out)
{
    const int b     = blockIdx.x >> 1;
    const int chunk = blockIdx.x & (NCHUNK - 1);
    const int t0    = chunk * CHUNK;
    const int t_end = t0 + CHUNK;
    const int j     = threadIdx.x;           // 0..255

    __shared__ __align__(128) float zsm[ZBYTES / 4];   // 32KB zero buffer

    // ---- any zero token in [0, t_end)?  one int4 load + one barrier-or ----
    const int n4 = t_end >> 2;                // 64 or 128 int4 words
    int pred = 0;
    if (j < n4) {
        const int4 v = reinterpret_cast<const int4*>(x + (size_t)b * T)[j];
        pred = (v.x == 0) | (v.y == 0) | (v.z == 0) | (v.w == 0);
    }

    // Fill zero buffer while the token load is in flight (always cheap).
    float4* zf4 = reinterpret_cast<float4*>(zsm);
    const float4 zv = make_float4(0.f, 0.f, 0.f, 0.f);
    #pragma unroll
    for (int i = 0; i < (ZBYTES / 16) / 256; i++)       // 2048 f4 / 256 thr = 8
        zf4[i * 256 + j] = zv;

    const int any = __syncthreads_or(pred);

    if (!any) {
        // ---------- common fast path: chunk output is exactly zero ----------
        // Make the generic-proxy SMEM zeros visible to the async proxy.
        asm volatile("fence.proxy.async.shared::cta;" ::: "memory");
        // Final-h tail (1KB) for fully-inactive batch: plain stores.
        if (chunk == NCHUNK - 1 && j < U / 4) {
            float4* hdst = reinterpret_cast<float4*>(out + (size_t)B * T * U + (size_t)b * U);
            hdst[j] = zv;
        }
        if (j == 0) {
            const unsigned saddr = smem_u32(zsm);
            char* gbase = reinterpret_cast<char*>(out + (size_t)b * T * U + (size_t)t0 * U);
            #pragma unroll
            for (int i = 0; i < BULKS_PER_CTA; i++) {
                asm volatile(
                    "cp.async.bulk.global.shared::cta.bulk_group [%0], [%1], %2;"
                    :: "l"(gbase + (size_t)i * ZBYTES), "r"(saddr), "n"(ZBYTES)
                    : "memory");
            }
            asm volatile("cp.async.bulk.commit_group;" ::: "memory");
            asm volatile("cp.async.bulk.wait_group 0;" ::: "memory");
        }
        return;
    }

    // ---------- rare general path: replay the masked LSTM up to t_end ----------
    __shared__ int   acts[T];
    __shared__ float h0s[U];
    __shared__ float h1s[U];
    __shared__ float zbuf[Z];
    __shared__ float embs[E];

    for (int t = j; t < t_end; t += 256)
        acts[t] = (x[(size_t)b * T + t] == 0);

    embs[j] = emb[j];        // embedding row of token 0
    h0s[j]  = 0.0f;
    h1s[j]  = 0.0f;
    __syncthreads();

    // Constant layer-0 x-contribution: xz = emb[0,:] @ k0 + b0.
    // Thread j owns gate columns 4j..4j+3 (float4 across Z).
    float4 xz = reinterpret_cast<const float4*>(b0)[j];
    for (int e = 0; e < E; e++) {
        const float  ev = embs[e];
        const float4 kv = reinterpret_cast<const float4*>(k0 + (size_t)e * Z)[j];
        xz.x += ev * kv.x; xz.y += ev * kv.y; xz.z += ev * kv.z; xz.w += ev * kv.w;
    }
    const float4 b1v = reinterpret_cast<const float4*>(b1)[j];

    float c0 = 0.0f, c1 = 0.0f;

    for (int t = 0; t < t_end; t++) {
        if (acts[t]) {
            // ---- layer 0: z = xz + h0 @ r0 ----
            float4 z = xz;
            #pragma unroll 4
            for (int k = 0; k < U; k++) {
                const float  hv = h0s[k];
                const float4 rv = reinterpret_cast<const float4*>(r0 + (size_t)k * Z)[j];
                z.x += hv * rv.x; z.y += hv * rv.y; z.z += hv * rv.z; z.w += hv * rv.w;
            }
            reinterpret_cast<float4*>(zbuf)[j] = z;
            __syncthreads();
            {
                const float ig = sigm (zbuf[0 * U + j]);
                const float fg = sigm (zbuf[1 * U + j]);
                const float gg = tanhf(zbuf[2 * U + j]);
                const float og = sigm (zbuf[3 * U + j]);
                c0 = fg * c0 + ig * gg;
                __syncthreads();                 // matvec reads of h0s fully done
                h0s[j] = og * tanhf(c0);
            }
            __syncthreads();

            // ---- layer 1: w = b1 + h0 @ k1 + h1 @ r1 ----
            float4 w = b1v;
            #pragma unroll 2
            for (int k = 0; k < U; k++) {
                const float  h0v = h0s[k];
                const float  h1v = h1s[k];
                const float4 kv = reinterpret_cast<const float4*>(k1 + (size_t)k * Z)[j];
                const float4 rv = reinterpret_cast<const float4*>(r1 + (size_t)k * Z)[j];
                w.x += h0v * kv.x + h1v * rv.x;
                w.y += h0v * kv.y + h1v * rv.y;
                w.z += h0v * kv.z + h1v * rv.z;
                w.w += h0v * kv.w + h1v * rv.w;
            }
            __syncthreads();                     // prior zbuf reads done
            reinterpret_cast<float4*>(zbuf)[j] = w;
            __syncthreads();
            {
                const float ig = sigm (zbuf[0 * U + j]);
                const float fg = sigm (zbuf[1 * U + j]);
                const float gg = tanhf(zbuf[2 * U + j]);
                const float og = sigm (zbuf[3 * U + j]);
                c1 = fg * c1 + ig * gg;
                __syncthreads();                 // matvec reads of h1s fully done
                h1s[j] = og * tanhf(c1);
            }
            __syncthreads();
        }
        if (t >= t0)
            out[(size_t)b * T * U + (size_t)t * U + j] = h1s[j];
    }

    if (chunk == NCHUNK - 1)                     // ran the full sequence
        out[(size_t)B * T * U + (size_t)b * U + j] = h1s[j];
}

extern "C" void kernel_launch(void* const* d_in, const int* in_sizes, int n_in,
                              void* d_out, int out_size)
{
    const int*   x   = (const int*)  d_in[0];
    const float* emb = (const float*)d_in[1];
    const float* k0  = (const float*)d_in[2];
    const float* r0  = (const float*)d_in[3];
    const float* b0  = (const float*)d_in[4];
    const float* k1  = (const float*)d_in[5];
    const float* r1  = (const float*)d_in[6];
    const float* b1  = (const float*)d_in[7];
    float* out = (float*)d_out;

    lstm_fused_kernel<<<B * NCHUNK, 256>>>(x, emb, k0, r0, b0, k1, r1, b1, out);
}

// round 5
// speedup vs baseline: 1.0239x; 1.0030x over previous
#include <cuda_runtime.h>
#include <math.h>

#define B 64
#define T 512
#define E 256
#define U 256
#define Z 1024      /* 4*U */

__device__ __forceinline__ float sigm(float v) { return 1.0f / (1.0f + expf(-v)); }

// Checker kernel: runs AFTER the memset node has zeroed the entire output.
// One CTA per batch. Keras masked-LSTM semantics: state updates ONLY at steps
// where token == 0 (mask True); elsewhere h/c carry and out[b,t] is carried h1.
// Hence out[b,t,:] == 0 exactly for every t before the first zero token, and a
// batch with no zero token contributes nothing beyond the memset. Common case:
// one vectorized token scan, zero stores, exit. Rare case: replay the sequence
// and overwrite out[b, t >= first_active, :] plus the final-h slot.
__global__ __launch_bounds__(256)
void lstm_checker_kernel(const int*   __restrict__ x,
                         const float* __restrict__ emb,
                         const float* __restrict__ k0,
                         const float* __restrict__ r0,
                         const float* __restrict__ b0,
                         const float* __restrict__ k1,
                         const float* __restrict__ r1,
                         const float* __restrict__ b1,
                         float*       __restrict__ out)
{
    const int b = blockIdx.x;
    const int j = threadIdx.x;                 // 0..255

    // ---- any zero token in this batch row? (512 tokens = 128 int4) ----
    int pred = 0;
    if (j < T / 4) {
        const int4 v = reinterpret_cast<const int4*>(x + (size_t)b * T)[j];
        pred = (v.x == 0) | (v.y == 0) | (v.z == 0) | (v.w == 0);
    }
    const int any = __syncthreads_or(pred);
    if (!any) return;                          // memset already produced the answer

    // ---------- rare general path: replay the masked LSTM ----------
    __shared__ int   acts[T];
    __shared__ float h0s[U];
    __shared__ float h1s[U];
    __shared__ float zbuf[Z];
    __shared__ float embs[E];
    __shared__ int   s_first;

    if (j == 0) s_first = T;
    __syncthreads();

    for (int t = j; t < T; t += 256) {
        const int a = (x[(size_t)b * T + t] == 0);
        acts[t] = a;
        if (a) atomicMin(&s_first, t);
    }

    embs[j] = emb[j];                          // embedding row of token 0
    h0s[j]  = 0.0f;
    h1s[j]  = 0.0f;
    __syncthreads();
    const int first = s_first;

    // Constant layer-0 x-contribution: xz = emb[0,:] @ k0 + b0.
    // Thread j owns gate columns 4j..4j+3 (float4 across Z).
    float4 xz = reinterpret_cast<const float4*>(b0)[j];
    for (int e = 0; e < E; e++) {
        const float  ev = embs[e];
        const float4 kv = reinterpret_cast<const float4*>(k0 + (size_t)e * Z)[j];
        xz.x += ev * kv.x; xz.y += ev * kv.y; xz.z += ev * kv.z; xz.w += ev * kv.w;
    }
    const float4 b1v = reinterpret_cast<const float4*>(b1)[j];

    float c0 = 0.0f, c1 = 0.0f;

    for (int t = first; t < T; t++) {
        if (acts[t]) {
            // ---- layer 0: z = xz + h0 @ r0 ----
            float4 z = xz;
            #pragma unroll 4
            for (int k = 0; k < U; k++) {
                const float  hv = h0s[k];
                const float4 rv = reinterpret_cast<const float4*>(r0 + (size_t)k * Z)[j];
                z.x += hv * rv.x; z.y += hv * rv.y; z.z += hv * rv.z; z.w += hv * rv.w;
            }
            reinterpret_cast<float4*>(zbuf)[j] = z;
            __syncthreads();
            {
                const float ig = sigm (zbuf[0 * U + j]);
                const float fg = sigm (zbuf[1 * U + j]);
                const float gg = tanhf(zbuf[2 * U + j]);
                const float og = sigm (zbuf[3 * U + j]);
                c0 = fg * c0 + ig * gg;
                __syncthreads();               // matvec reads of h0s fully done
                h0s[j] = og * tanhf(c0);
            }
            __syncthreads();

            // ---- layer 1: w = b1 + h0 @ k1 + h1 @ r1 ----
            float4 w = b1v;
            #pragma unroll 2
            for (int k = 0; k < U; k++) {
                const float  h0v = h0s[k];
                const float  h1v = h1s[k];
                const float4 kv = reinterpret_cast<const float4*>(k1 + (size_t)k * Z)[j];
                const float4 rv = reinterpret_cast<const float4*>(r1 + (size_t)k * Z)[j];
                w.x += h0v * kv.x + h1v * rv.x;
                w.y += h0v * kv.y + h1v * rv.y;
                w.z += h0v * kv.z + h1v * rv.z;
                w.w += h0v * kv.w + h1v * rv.w;
            }
            __syncthreads();                   // prior zbuf reads done
            reinterpret_cast<float4*>(zbuf)[j] = w;
            __syncthreads();
            {
                const float ig = sigm (zbuf[0 * U + j]);
                const float fg = sigm (zbuf[1 * U + j]);
                const float gg = tanhf(zbuf[2 * U + j]);
                const float og = sigm (zbuf[3 * U + j]);
                c1 = fg * c1 + ig * gg;
                __syncthreads();               // matvec reads of h1s fully done
                h1s[j] = og * tanhf(c1);
            }
            __syncthreads();
        }
        // From first active step onward the carried h1 may be nonzero: write it.
        out[(size_t)b * T * U + (size_t)t * U + j] = h1s[j];
    }

    // Final hidden state (memset already handled the all-inactive case).
    out[(size_t)B * T * U + (size_t)b * U + j] = h1s[j];
}

extern "C" void kernel_launch(void* const* d_in, const int* in_sizes, int n_in,
                              void* d_out, int out_size)
{
    const int*   x   = (const int*)  d_in[0];
    const float* emb = (const float*)d_in[1];
    const float* k0  = (const float*)d_in[2];
    const float* r0  = (const float*)d_in[3];
    const float* b0  = (const float*)d_in[4];
    const float* k1  = (const float*)d_in[5];
    const float* r1  = (const float*)d_in[6];
    const float* b1  = (const float*)d_in[7];
    float* out = (float*)d_out;

    // Memset node: zero the full output (33.5MB + final-h) on the copy path,
    // bypassing the per-SM store-egress wall measured in R1-R4.
    cudaMemsetAsync(out, 0, (size_t)out_size * sizeof(float), 0);

    // Dependent checker: common case exits after one vectorized token scan;
    // rare case replays the masked LSTM and overwrites the nonzero suffix.
    lstm_checker_kernel<<<B, 256>>>(x, emb, k0, r0, b0, k1, r1, b1, out);
}